// round 16
// baseline (speedup 1.0000x reference)
#include <cuda_runtime.h>
#include <math.h>

// Problem constants: C=128, B=32, H=W=64.
// Per-LSTM: N = 2048 rows, T = 64 steps, C = 128 channels, 4C = 512 gates.
#define NPLANE 16777216  // 2048*64*128
#define ROWP 68          // padded row stride for v-buffers (16B-aligned, 4-way max conflict)

typedef unsigned long long ull;

// Scratch (device globals; no runtime allocation).
__device__ float g_xT[2][NPLANE];        // [0]=vertical [1]=horizontal, layout [n][t][c]
__device__ float g_H[4][NPLANE];         // LSTM hidden outputs {vf, vb, hf, hb}, [n][t][c]
__device__ float4 g_W4[4][256 * 128];    // lstm weights: [lstm][k*128+ch] = (Wi,Wf,Wg,Wo)[ch] at col k
                                         // k<128 from Wih, k>=128 from Whh (concat over [x|h])
__device__ float4 g_Wc4[4][128 * 32];    // conv weights: [cv][k*32+to] = W[{to,to+32,to+64,to+96}][k]

struct LstmParams {
    const float* Wih[4];
    const float* Whh[4];
    const float* bias[4];
};
struct ConvParams {
    const float* w[4];
    const float* b[4];
};

// --------------------------------------------------------------------------
// Packed f32x2 helpers (Blackwell FFMA2 — only reachable via PTX) + cp.async.
// --------------------------------------------------------------------------
__device__ __forceinline__ ull dup2(float w) {
    ull r; asm("mov.b64 %0, {%1, %1};" : "=l"(r) : "f"(w)); return r;
}
__device__ __forceinline__ void fma2(ull& d, ull a, ull b) {
    asm("fma.rn.f32x2 %0, %1, %2, %0;" : "+l"(d) : "l"(a), "l"(b));
}
__device__ __forceinline__ float2 unpack2(ull a) {
    float2 u; asm("mov.b64 {%0, %1}, %2;" : "=f"(u.x), "=f"(u.y) : "l"(a)); return u;
}
__device__ __forceinline__ unsigned smem_u32(const void* p) {
    unsigned a;
    asm("{ .reg .u64 t; cvta.to.shared.u64 t, %1; cvt.u32.u64 %0, t; }" : "=r"(a) : "l"(p));
    return a;
}
__device__ __forceinline__ void cp16(unsigned dst, const void* src) {
    asm volatile("cp.async.cg.shared.global [%0], [%1], 16;" :: "r"(dst), "l"(src));
}
#define CP_COMMIT() asm volatile("cp.async.commit_group;" ::: "memory")
#define CP_WAIT0()  asm volatile("cp.async.wait_group 0;" ::: "memory")

__device__ __forceinline__ float sigf(float x)  { return 1.0f / (1.0f + __expf(-x)); }
__device__ __forceinline__ float tanhf_(float x){ return 2.0f / (1.0f + __expf(-2.0f * x)) - 1.0f; }

// --------------------------------------------------------------------------
// Kernel 0a: pack LSTM weights into gate-quadruple float4 layout.
// idx = k*128 + ch -> (W[ch][k], W[ch+128][k], W[ch+256][k], W[ch+384][k]).
// --------------------------------------------------------------------------
__global__ __launch_bounds__(256) void pack_lstm_kernel(LstmParams P) {
    int lstm = blockIdx.y;
    int idx = blockIdx.x * 256 + threadIdx.x;   // 0..32767
    int k = idx >> 7;
    int ch = idx & 127;
    const float* __restrict__ W = (k < 128) ? P.Wih[lstm] : P.Whh[lstm];
    int kk = k & 127;
    g_W4[lstm][idx] = make_float4(W[(size_t)ch * 128 + kk],
                                  W[(size_t)(ch + 128) * 128 + kk],
                                  W[(size_t)(ch + 256) * 128 + kk],
                                  W[(size_t)(ch + 384) * 128 + kk]);
}

// Kernel 0b: pack conv weights: [cv][k*32+to] = W[{to,to+32,to+64,to+96}][k]
__global__ __launch_bounds__(256) void pack_conv_kernel(ConvParams P) {
    int cv = blockIdx.y;
    int idx = blockIdx.x * 256 + threadIdx.x;   // 0..4095
    int k = idx >> 5;
    int to = idx & 31;
    const float* __restrict__ W = P.w[cv];
    g_Wc4[cv][idx] = make_float4(W[(size_t)to * 128 + k],
                                 W[(size_t)(to + 32) * 128 + k],
                                 W[(size_t)(to + 64) * 128 + k],
                                 W[(size_t)(to + 96) * 128 + k]);
}

// --------------------------------------------------------------------------
// Kernel 1: transpose x[B,C,H,W] into the two [n][t][c] scan layouts.
// --------------------------------------------------------------------------
__global__ __launch_bounds__(256) void transpose_kernel(const float* __restrict__ x) {
    __shared__ float s[128 * 65];
    int b = blockIdx.x >> 6;
    int h = blockIdx.x & 63;
    int tid = threadIdx.x;

    const float* xb = x + (size_t)b * 128 * 4096 + (size_t)h * 64;
    for (int idx = tid; idx < 128 * 64; idx += 256) {
        int c = idx >> 6, w = idx & 63;
        s[c * 65 + w] = xb[(size_t)c * 4096 + w];
    }
    __syncthreads();

    float* xv = g_xT[0] + (size_t)(b * 64 + h) * 64 * 128;
    for (int idx = tid; idx < 128 * 64; idx += 256) {
        int w = idx >> 7, c = idx & 127;
        xv[w * 128 + c] = s[c * 65 + w];
    }
    float* xh = g_xT[1] + (size_t)b * 64 * 64 * 128 + (size_t)h * 128;
    for (int idx = tid; idx < 128 * 64; idx += 256) {
        int w = idx >> 7, c = idx & 127;
        xh[(size_t)w * 64 * 128 + c] = s[c * 65 + w];
    }
}

// --------------------------------------------------------------------------
// Kernel 2: fused LSTM recurrence, FFMA2 + cp.async weight pipeline.
// grid = (32 row-blocks, 4 LSTMs) = 128 CTAs, 1024 thr, 1 CTA/SM, ONE wave.
// CTA owns 64 rows x 64 steps -> weight smem reads amortize over 2x the rows
// (crossbar drops from ~100% to ~81% of FMA), weight L2 stream halves.
// Thread (ch=tid&127, rg=tid>>7 in 0..7): gate quad (i,f,g,o) of channel ch
// for rows rg*8..rg*8+7 (4 row-pairs, 16 f32x2 accumulators).
// v-buffers sX/sH use row-stride ROWP=68: 16B-aligned ulonglong2 reads,
// staging/h stores are 4-way (not 32-way) bank conflicted.
// Weights stream via cp.async in 32 chunks of 8 k (16 KB), double-buffered.
// Dynamic smem 134 KB: sX 34K + sH 2x34K + sW 2x16K.
// --------------------------------------------------------------------------
__global__ __launch_bounds__(1024, 1) void lstm_kernel(LstmParams P) {
    int lstm = blockIdx.y;
    int n0 = blockIdx.x * 64;

    const float4* __restrict__ W4   = g_W4[lstm];
    const float*  __restrict__ bias = P.bias[lstm];
    const float*  __restrict__ xT   = g_xT[lstm >> 1];
    float*        __restrict__ Hout = g_H[lstm];
    const bool rev = (lstm & 1) != 0;

    extern __shared__ float sm[];
    float*  sX = sm;                            // [128][ROWP]      (34816 B)
    float*  sH = sm + 128 * ROWP;               // [2][128][ROWP]   (69632 B)
    float4* sW = (float4*)(sm + 3 * 128 * ROWP);// [2][8][128]      (32768 B)
    unsigned sWu = smem_u32(sW);

    int tid = threadIdx.x;
    int ch = tid & 127;
    int rg = tid >> 7;          // 0..7
    int r0 = rg * 8;

    float bi_f = bias[ch];
    float bf_f = bias[ch + 128];
    float bg_f = bias[ch + 256];
    float bo_f = bias[ch + 384];

    float c[8];
    #pragma unroll
    for (int r = 0; r < 8; r++) c[r] = 0.f;

    // zero h buffer 0 (h[-1]); stage x(0); prefetch weight chunk 0
    #pragma unroll
    for (int r = 0; r < 8; r++) sH[ch * ROWP + r0 + r] = 0.f;
    {
        int t0 = rev ? 63 : 0;
        const float* xsrc = xT + ((size_t)(n0 + r0) * 64 + t0) * 128 + ch;
        #pragma unroll
        for (int r = 0; r < 8; r++)
            sX[ch * ROWP + r0 + r] = xsrc[(size_t)r * 8192];
    }
    cp16(sWu + (unsigned)tid * 16, W4 + tid);   // 1024 threads = 16 KB chunk
    CP_COMMIT();

    for (int tt = 0; tt < 64; ++tt) {
        int t = rev ? 63 - tt : tt;
        int hbuf = tt & 1;

        ull ai[4], af[4], ag[4], ao[4];
        {
            ull bi = dup2(bi_f), bf = dup2(bf_f), bg = dup2(bg_f), bo = dup2(bo_f);
            #pragma unroll
            for (int rp = 0; rp < 4; rp++) { ai[rp] = bi; af[rp] = bf; ag[rp] = bg; ao[rp] = bo; }
        }

        for (int cc = 0; cc < 32; ++cc) {
            CP_WAIT0();          // chunk cc resident in sW[cc&1]
            __syncthreads();     // + orders x-stage / h-writes at cc==0

            // prefetch chunk (cc+1)&31 into the other buffer
            {
                int nc = (cc + 1) & 31;
                cp16(sWu + (unsigned)((((nc & 1) << 10) + tid) * 16), W4 + nc * 1024 + tid);
                CP_COMMIT();
            }

            const float* vb = (cc < 16) ? (sX + cc * 8 * ROWP)
                                        : (sH + hbuf * 128 * ROWP + (cc - 16) * 8 * ROWP);
            const float4* wb = sW + ((cc & 1) << 10);

            #pragma unroll
            for (int k8 = 0; k8 < 8; ++k8) {
                float4 w = wb[k8 * 128 + ch];                 // LDS.128, conflict-free
                ull wi = dup2(w.x), wf = dup2(w.y), wg = dup2(w.z), wo = dup2(w.w);
                const ulonglong2* vp = (const ulonglong2*)(vb + k8 * ROWP + r0);  // 16B-aligned
                ulonglong2 vA = vp[0];                        // row-pairs 0,1 (broadcast)
                ulonglong2 vB = vp[1];                        // row-pairs 2,3
                fma2(ai[0], vA.x, wi); fma2(af[0], vA.x, wf); fma2(ag[0], vA.x, wg); fma2(ao[0], vA.x, wo);
                fma2(ai[1], vA.y, wi); fma2(af[1], vA.y, wf); fma2(ag[1], vA.y, wg); fma2(ao[1], vA.y, wo);
                fma2(ai[2], vB.x, wi); fma2(af[2], vB.x, wf); fma2(ag[2], vB.x, wg); fma2(ao[2], vB.x, wo);
                fma2(ai[3], vB.y, wi); fma2(af[3], vB.y, wf); fma2(ag[3], vB.y, wg); fma2(ao[3], vB.y, wo);
            }
        }

        // ---- gate combine, fully local; h[t] -> other h buffer + gmem ----
        float* __restrict__ Hn = sH + (hbuf ^ 1) * 128 * ROWP;
        #pragma unroll
        for (int rp = 0; rp < 4; rp++) {
            float2 zi = unpack2(ai[rp]);
            float2 zf = unpack2(af[rp]);
            float2 zg = unpack2(ag[rp]);
            float2 zo = unpack2(ao[rp]);

            int row = r0 + 2 * rp;
            c[2 * rp]     = sigf(zf.x) * c[2 * rp]     + sigf(zi.x) * tanhf_(zg.x);
            c[2 * rp + 1] = sigf(zf.y) * c[2 * rp + 1] + sigf(zi.y) * tanhf_(zg.y);
            float h0 = sigf(zo.x) * tanhf_(c[2 * rp]);
            float h1 = sigf(zo.y) * tanhf_(c[2 * rp + 1]);

            Hn[ch * ROWP + row]     = h0;
            Hn[ch * ROWP + row + 1] = h1;
            Hout[((size_t)(n0 + row) * 64 + t) * 128 + ch]     = h0;   // coalesced
            Hout[((size_t)(n0 + row + 1) * 64 + t) * 128 + ch] = h1;
        }

        // stage x for next step (chunks 16..31 of this step never read sX;
        // next step's cc==0 barrier orders these writes before reads)
        {
            int ttn = (tt < 63) ? tt + 1 : 63;
            int tn = rev ? 63 - ttn : ttn;
            const float* xsrc = xT + ((size_t)(n0 + r0) * 64 + tn) * 128 + ch;
            #pragma unroll
            for (int r = 0; r < 8; r++)
                sX[ch * ROWP + r0 + r] = xsrc[(size_t)r * 8192];
        }
    }
    CP_WAIT0();   // drain the final (unused) prefetch before exit
}

// --------------------------------------------------------------------------
// Kernel 3: 1x1 conv with FFMA2. grid = (4096 tiles, 4 outputs), 128 threads.
// CTA: 32 positions x 128 outs. Thread: 4 outs x 4 position-pairs (16 f32x2).
// Hs stored transposed [c][pos] (pad 34) so a position-pair is one LDS.64.
// --------------------------------------------------------------------------
__global__ __launch_bounds__(128) void conv_kernel(ConvParams P, float* __restrict__ out) {
    int kk = blockIdx.y;                                  // 0:down 1:up 2:right 3:left
    int src = (kk == 0) ? 1 : ((kk == 1) ? 0 : kk);       // down<-vb, up<-vf, right<-hf, left<-hb
    const float*  __restrict__ Hg   = g_H[src];
    const float4* __restrict__ W4   = g_Wc4[kk];
    const float*  __restrict__ bias = P.b[kk];
    float* __restrict__ outk = out + (size_t)kk * NPLANE;

    __shared__ float Hs[128 * 34];                        // [c][pos], pad 34
    int tid = threadIdx.x;
    int p0 = blockIdx.x * 32;

    for (int idx = tid; idx < 32 * 128; idx += 128) {
        int p = idx >> 7, c = idx & 127;                  // coalesced gmem read
        Hs[c * 34 + p] = Hg[(size_t)(p0 + p) * 128 + c];
    }
    __syncthreads();

    int tp = tid & 3;    // pair base: pairs {tp, tp+4, tp+8, tp+12}
    int to = tid >> 2;   // outs: {to, to+32, to+64, to+96}

    ull acc[4][4];       // [out][pair]
    {
        ull b0 = dup2(bias[to]);
        ull b1 = dup2(bias[to + 32]);
        ull b2 = dup2(bias[to + 64]);
        ull b3 = dup2(bias[to + 96]);
        #pragma unroll
        for (int i = 0; i < 4; i++) { acc[0][i] = b0; acc[1][i] = b1; acc[2][i] = b2; acc[3][i] = b3; }
    }

    #pragma unroll 4
    for (int k = 0; k < 128; k++) {
        float4 w = W4[k * 32 + to];
        ull w0 = dup2(w.x), w1 = dup2(w.y), w2 = dup2(w.z), w3 = dup2(w.w);
        const ull* hp = (const ull*)(Hs + k * 34) + tp;
        #pragma unroll
        for (int i = 0; i < 4; i++) {
            ull v = hp[i * 4];
            fma2(acc[0][i], v, w0);
            fma2(acc[1][i], v, w1);
            fma2(acc[2][i], v, w2);
            fma2(acc[3][i], v, w3);
        }
    }

    #pragma unroll
    for (int i = 0; i < 4; i++) {
        int p = p0 + 2 * (tp + 4 * i);
        int b = p >> 12, q = p & 4095;
        float* ob = outk + (size_t)b * 128 * 4096 + q;
        #pragma unroll
        for (int j = 0; j < 4; j++) {
            float2 z = unpack2(acc[j][i]);
            *(float2*)(ob + (size_t)(to + 32 * j) * 4096) = z;   // STG.64, 8B-aligned
        }
    }
}

// --------------------------------------------------------------------------
// Launch. Inputs (metadata order):
// 0:x  1-3:vWih_f,vWhh_f,vb_f  4-6:vWih_b,vWhh_b,vb_b
// 7-9:hWih_f,hWhh_f,hb_f  10-12:hWih_b,hWhh_b,hb_b
// 13..20: (w,b) for down, up, right, left
// --------------------------------------------------------------------------
extern "C" void kernel_launch(void* const* d_in, const int* in_sizes, int n_in,
                              void* d_out, int out_size) {
    (void)in_sizes; (void)n_in; (void)out_size;
    const float* x = (const float*)d_in[0];

    LstmParams LP;
    for (int l = 0; l < 4; l++) {
        LP.Wih[l]  = (const float*)d_in[1 + 3 * l];
        LP.Whh[l]  = (const float*)d_in[2 + 3 * l];
        LP.bias[l] = (const float*)d_in[3 + 3 * l];
    }
    ConvParams CP;
    for (int k = 0; k < 4; k++) {
        CP.w[k] = (const float*)d_in[13 + 2 * k];
        CP.b[k] = (const float*)d_in[14 + 2 * k];
    }

    const int lstm_smem = (3 * 128 * ROWP) * 4 + 32768;   // 137216 B
    cudaFuncSetAttribute(lstm_kernel, cudaFuncAttributeMaxDynamicSharedMemorySize, lstm_smem);

    pack_lstm_kernel<<<dim3(128, 4), 256>>>(LP);
    pack_conv_kernel<<<dim3(16, 4), 256>>>(CP);
    transpose_kernel<<<2048, 256>>>(x);
    lstm_kernel<<<dim3(32, 4), 1024, lstm_smem>>>(LP);
    conv_kernel<<<dim3(4096, 4), 128>>>(CP, (float*)d_out);
}

// round 17
// speedup vs baseline: 1.8297x; 1.8297x over previous
#include <cuda_runtime.h>
#include <math.h>

// Problem constants: C=128, B=32, H=W=64.
// Per-LSTM: N = 2048 rows, T = 64 steps, C = 128 channels, 4C = 512 gates.
#define NPLANE 16777216  // 2048*64*128
#define ROWP 36          // padded row stride for v-buffers: 144 B (16B-aligned),
                         // store bank = (4*ch + r) % 32 -> 8-way, not 32-way

typedef unsigned long long ull;

// Scratch (device globals; no runtime allocation).
__device__ float g_xT[2][NPLANE];        // [0]=vertical [1]=horizontal, layout [n][t][c]
__device__ float g_H[4][NPLANE];         // LSTM hidden outputs {vf, vb, hf, hb}, [n][t][c]
__device__ float4 g_W4[4][256 * 128];    // lstm weights: [lstm][k*128+ch] = (Wi,Wf,Wg,Wo)[ch] at col k
                                         // k<128 from Wih, k>=128 from Whh (concat over [x|h])
__device__ float4 g_Wc4[4][128 * 32];    // conv weights: [cv][k*32+to] = W[{to,to+32,to+64,to+96}][k]

struct LstmParams {
    const float* Wih[4];
    const float* Whh[4];
    const float* bias[4];
};
struct ConvParams {
    const float* w[4];
    const float* b[4];
};

// --------------------------------------------------------------------------
// Packed f32x2 helpers (Blackwell FFMA2 — only reachable via PTX) + cp.async.
// --------------------------------------------------------------------------
__device__ __forceinline__ ull dup2(float w) {
    ull r; asm("mov.b64 %0, {%1, %1};" : "=l"(r) : "f"(w)); return r;
}
__device__ __forceinline__ void fma2(ull& d, ull a, ull b) {
    asm("fma.rn.f32x2 %0, %1, %2, %0;" : "+l"(d) : "l"(a), "l"(b));
}
__device__ __forceinline__ float2 unpack2(ull a) {
    float2 u; asm("mov.b64 {%0, %1}, %2;" : "=f"(u.x), "=f"(u.y) : "l"(a)); return u;
}
__device__ __forceinline__ unsigned smem_u32(const void* p) {
    unsigned a;
    asm("{ .reg .u64 t; cvta.to.shared.u64 t, %1; cvt.u32.u64 %0, t; }" : "=r"(a) : "l"(p));
    return a;
}
__device__ __forceinline__ void cp16(unsigned dst, const void* src) {
    asm volatile("cp.async.cg.shared.global [%0], [%1], 16;" :: "r"(dst), "l"(src));
}
#define CP_COMMIT() asm volatile("cp.async.commit_group;" ::: "memory")
#define CP_WAIT0()  asm volatile("cp.async.wait_group 0;" ::: "memory")

__device__ __forceinline__ float sigf(float x)  { return 1.0f / (1.0f + __expf(-x)); }
__device__ __forceinline__ float tanhf_(float x){ return 2.0f / (1.0f + __expf(-2.0f * x)) - 1.0f; }

// --------------------------------------------------------------------------
// Kernel 0a: pack LSTM weights into gate-quadruple float4 layout.
// idx = k*128 + ch -> (W[ch][k], W[ch+128][k], W[ch+256][k], W[ch+384][k]).
// --------------------------------------------------------------------------
__global__ __launch_bounds__(256) void pack_lstm_kernel(LstmParams P) {
    int lstm = blockIdx.y;
    int idx = blockIdx.x * 256 + threadIdx.x;   // 0..32767
    int k = idx >> 7;
    int ch = idx & 127;
    const float* __restrict__ W = (k < 128) ? P.Wih[lstm] : P.Whh[lstm];
    int kk = k & 127;
    g_W4[lstm][idx] = make_float4(W[(size_t)ch * 128 + kk],
                                  W[(size_t)(ch + 128) * 128 + kk],
                                  W[(size_t)(ch + 256) * 128 + kk],
                                  W[(size_t)(ch + 384) * 128 + kk]);
}

// Kernel 0b: pack conv weights: [cv][k*32+to] = W[{to,to+32,to+64,to+96}][k]
__global__ __launch_bounds__(256) void pack_conv_kernel(ConvParams P) {
    int cv = blockIdx.y;
    int idx = blockIdx.x * 256 + threadIdx.x;   // 0..4095
    int k = idx >> 5;
    int to = idx & 31;
    const float* __restrict__ W = P.w[cv];
    g_Wc4[cv][idx] = make_float4(W[(size_t)to * 128 + k],
                                 W[(size_t)(to + 32) * 128 + k],
                                 W[(size_t)(to + 64) * 128 + k],
                                 W[(size_t)(to + 96) * 128 + k]);
}

// --------------------------------------------------------------------------
// Kernel 1: transpose x[B,C,H,W] into the two [n][t][c] scan layouts.
// --------------------------------------------------------------------------
__global__ __launch_bounds__(256) void transpose_kernel(const float* __restrict__ x) {
    __shared__ float s[128 * 65];
    int b = blockIdx.x >> 6;
    int h = blockIdx.x & 63;
    int tid = threadIdx.x;

    const float* xb = x + (size_t)b * 128 * 4096 + (size_t)h * 64;
    for (int idx = tid; idx < 128 * 64; idx += 256) {
        int c = idx >> 6, w = idx & 63;
        s[c * 65 + w] = xb[(size_t)c * 4096 + w];
    }
    __syncthreads();

    float* xv = g_xT[0] + (size_t)(b * 64 + h) * 64 * 128;
    for (int idx = tid; idx < 128 * 64; idx += 256) {
        int w = idx >> 7, c = idx & 127;
        xv[w * 128 + c] = s[c * 65 + w];
    }
    float* xh = g_xT[1] + (size_t)b * 64 * 64 * 128 + (size_t)h * 128;
    for (int idx = tid; idx < 128 * 64; idx += 256) {
        int w = idx >> 7, c = idx & 127;
        xh[(size_t)w * 64 * 128 + c] = s[c * 65 + w];
    }
}

// --------------------------------------------------------------------------
// Kernel 2: fused LSTM recurrence, FFMA2 + cp.async weight pipeline.
// REVERTED to the R13 shape (2 CTAs/SM is the latency-hiding mechanism:
// one CTA computes while the other sits in wait/barrier) + ROWP padding.
// grid = (64 row-blocks, 4 LSTMs) = 256 CTAs, 512 thr, 2 CTAs/SM, ONE wave.
// CTA owns 32 rows x 64 steps. Thread (ch=tid&127, rg=tid>>7): gate quad
// (i,f,g,o) of channel ch for rows rg*8..rg*8+7 (4 row-pairs, 16 f32x2 accs).
// Weights stream via cp.async in 32 chunks of 8 k (16 KB), double-buffered.
// Dynamic smem 86 KB: sX 18K [k<128][ROWP] + sH 2x18K + sW 2x16K.
// --------------------------------------------------------------------------
__global__ __launch_bounds__(512, 2) void lstm_kernel(LstmParams P) {
    int lstm = blockIdx.y;
    int n0 = blockIdx.x * 32;

    const float4* __restrict__ W4   = g_W4[lstm];
    const float*  __restrict__ bias = P.bias[lstm];
    const float*  __restrict__ xT   = g_xT[lstm >> 1];
    float*        __restrict__ Hout = g_H[lstm];
    const bool rev = (lstm & 1) != 0;

    extern __shared__ float sm[];
    float*  sX = sm;                              // [128][ROWP]      (18432 B)
    float*  sH = sm + 128 * ROWP;                 // [2][128][ROWP]   (36864 B)
    float4* sW = (float4*)(sm + 3 * 128 * ROWP);  // [2][8][128]      (32768 B)
    unsigned sWu = smem_u32(sW);

    int tid = threadIdx.x;
    int ch = tid & 127;
    int rg = tid >> 7;          // 0..3
    int r0 = rg * 8;

    float bi_f = bias[ch];
    float bf_f = bias[ch + 128];
    float bg_f = bias[ch + 256];
    float bo_f = bias[ch + 384];

    float c[8];
    #pragma unroll
    for (int r = 0; r < 8; r++) c[r] = 0.f;

    // zero h buffer 0 (h[-1]); stage x(0); prefetch weight chunk 0
    #pragma unroll
    for (int r = 0; r < 8; r++) sH[ch * ROWP + r0 + r] = 0.f;
    {
        int t0 = rev ? 63 : 0;
        const float* xsrc = xT + ((size_t)(n0 + r0) * 64 + t0) * 128 + ch;
        #pragma unroll
        for (int r = 0; r < 8; r++)
            sX[ch * ROWP + r0 + r] = xsrc[(size_t)r * 8192];
    }
    cp16(sWu + (unsigned)tid * 16, W4 + tid);
    cp16(sWu + (unsigned)(tid + 512) * 16, W4 + tid + 512);
    CP_COMMIT();

    for (int tt = 0; tt < 64; ++tt) {
        int t = rev ? 63 - tt : tt;
        int hbuf = tt & 1;

        ull ai[4], af[4], ag[4], ao[4];
        {
            ull bi = dup2(bi_f), bf = dup2(bf_f), bg = dup2(bg_f), bo = dup2(bo_f);
            #pragma unroll
            for (int rp = 0; rp < 4; rp++) { ai[rp] = bi; af[rp] = bf; ag[rp] = bg; ao[rp] = bo; }
        }

        for (int cc = 0; cc < 32; ++cc) {
            CP_WAIT0();          // chunk cc resident in sW[cc&1]
            __syncthreads();     // + orders x-stage / h-writes at cc==0

            // prefetch chunk (cc+1)&31 into the other buffer
            {
                int nc = (cc + 1) & 31;
                const float4* src = W4 + nc * 1024 + tid;
                unsigned dst = sWu + (unsigned)((((nc & 1) << 10) + tid) * 16);
                cp16(dst, src);
                cp16(dst + 512 * 16, src + 512);
                CP_COMMIT();
            }

            const float* vb = (cc < 16) ? (sX + cc * 8 * ROWP)
                                        : (sH + hbuf * 128 * ROWP + (cc - 16) * 8 * ROWP);
            const float4* wb = sW + ((cc & 1) << 10);

            #pragma unroll
            for (int k8 = 0; k8 < 8; ++k8) {
                float4 w = wb[k8 * 128 + ch];                 // LDS.128, conflict-free
                ull wi = dup2(w.x), wf = dup2(w.y), wg = dup2(w.z), wo = dup2(w.w);
                const ulonglong2* vp = (const ulonglong2*)(vb + k8 * ROWP + r0);  // 16B-aligned
                ulonglong2 vA = vp[0];                        // row-pairs 0,1 (broadcast)
                ulonglong2 vB = vp[1];                        // row-pairs 2,3
                fma2(ai[0], vA.x, wi); fma2(af[0], vA.x, wf); fma2(ag[0], vA.x, wg); fma2(ao[0], vA.x, wo);
                fma2(ai[1], vA.y, wi); fma2(af[1], vA.y, wf); fma2(ag[1], vA.y, wg); fma2(ao[1], vA.y, wo);
                fma2(ai[2], vB.x, wi); fma2(af[2], vB.x, wf); fma2(ag[2], vB.x, wg); fma2(ao[2], vB.x, wo);
                fma2(ai[3], vB.y, wi); fma2(af[3], vB.y, wf); fma2(ag[3], vB.y, wg); fma2(ao[3], vB.y, wo);
            }
        }

        // ---- gate combine, fully local; h[t] -> other h buffer + gmem ----
        float* __restrict__ Hn = sH + (hbuf ^ 1) * 128 * ROWP;
        #pragma unroll
        for (int rp = 0; rp < 4; rp++) {
            float2 zi = unpack2(ai[rp]);
            float2 zf = unpack2(af[rp]);
            float2 zg = unpack2(ag[rp]);
            float2 zo = unpack2(ao[rp]);

            int row = r0 + 2 * rp;
            c[2 * rp]     = sigf(zf.x) * c[2 * rp]     + sigf(zi.x) * tanhf_(zg.x);
            c[2 * rp + 1] = sigf(zf.y) * c[2 * rp + 1] + sigf(zi.y) * tanhf_(zg.y);
            float h0 = sigf(zo.x) * tanhf_(c[2 * rp]);
            float h1 = sigf(zo.y) * tanhf_(c[2 * rp + 1]);

            Hn[ch * ROWP + row]     = h0;
            Hn[ch * ROWP + row + 1] = h1;
            Hout[((size_t)(n0 + row) * 64 + t) * 128 + ch]     = h0;   // coalesced
            Hout[((size_t)(n0 + row + 1) * 64 + t) * 128 + ch] = h1;
        }

        // stage x for next step (chunks 16..31 of this step never read sX;
        // next step's cc==0 barrier orders these writes before reads)
        {
            int ttn = (tt < 63) ? tt + 1 : 63;
            int tn = rev ? 63 - ttn : ttn;
            const float* xsrc = xT + ((size_t)(n0 + r0) * 64 + tn) * 128 + ch;
            #pragma unroll
            for (int r = 0; r < 8; r++)
                sX[ch * ROWP + r0 + r] = xsrc[(size_t)r * 8192];
        }
    }
    CP_WAIT0();   // drain the final (unused) prefetch before exit
}

// --------------------------------------------------------------------------
// Kernel 3: 1x1 conv with FFMA2. grid = (4096 tiles, 4 outputs), 128 threads.
// CTA: 32 positions x 128 outs. Thread: 4 outs x 4 position-pairs (16 f32x2).
// Hs stored transposed [c][pos] (pad 34) so a position-pair is one LDS.64.
// --------------------------------------------------------------------------
__global__ __launch_bounds__(128) void conv_kernel(ConvParams P, float* __restrict__ out) {
    int kk = blockIdx.y;                                  // 0:down 1:up 2:right 3:left
    int src = (kk == 0) ? 1 : ((kk == 1) ? 0 : kk);       // down<-vb, up<-vf, right<-hf, left<-hb
    const float*  __restrict__ Hg   = g_H[src];
    const float4* __restrict__ W4   = g_Wc4[kk];
    const float*  __restrict__ bias = P.b[kk];
    float* __restrict__ outk = out + (size_t)kk * NPLANE;

    __shared__ float Hs[128 * 34];                        // [c][pos], pad 34
    int tid = threadIdx.x;
    int p0 = blockIdx.x * 32;

    for (int idx = tid; idx < 32 * 128; idx += 128) {
        int p = idx >> 7, c = idx & 127;                  // coalesced gmem read
        Hs[c * 34 + p] = Hg[(size_t)(p0 + p) * 128 + c];
    }
    __syncthreads();

    int tp = tid & 3;    // pair base: pairs {tp, tp+4, tp+8, tp+12}
    int to = tid >> 2;   // outs: {to, to+32, to+64, to+96}

    ull acc[4][4];       // [out][pair]
    {
        ull b0 = dup2(bias[to]);
        ull b1 = dup2(bias[to + 32]);
        ull b2 = dup2(bias[to + 64]);
        ull b3 = dup2(bias[to + 96]);
        #pragma unroll
        for (int i = 0; i < 4; i++) { acc[0][i] = b0; acc[1][i] = b1; acc[2][i] = b2; acc[3][i] = b3; }
    }

    #pragma unroll 4
    for (int k = 0; k < 128; k++) {
        float4 w = W4[k * 32 + to];
        ull w0 = dup2(w.x), w1 = dup2(w.y), w2 = dup2(w.z), w3 = dup2(w.w);
        const ull* hp = (const ull*)(Hs + k * 34) + tp;
        #pragma unroll
        for (int i = 0; i < 4; i++) {
            ull v = hp[i * 4];
            fma2(acc[0][i], v, w0);
            fma2(acc[1][i], v, w1);
            fma2(acc[2][i], v, w2);
            fma2(acc[3][i], v, w3);
        }
    }

    #pragma unroll
    for (int i = 0; i < 4; i++) {
        int p = p0 + 2 * (tp + 4 * i);
        int b = p >> 12, q = p & 4095;
        float* ob = outk + (size_t)b * 128 * 4096 + q;
        #pragma unroll
        for (int j = 0; j < 4; j++) {
            float2 z = unpack2(acc[j][i]);
            *(float2*)(ob + (size_t)(to + 32 * j) * 4096) = z;   // STG.64, 8B-aligned
        }
    }
}

// --------------------------------------------------------------------------
// Launch. Inputs (metadata order):
// 0:x  1-3:vWih_f,vWhh_f,vb_f  4-6:vWih_b,vWhh_b,vb_b
// 7-9:hWih_f,hWhh_f,hb_f  10-12:hWih_b,hWhh_b,hb_b
// 13..20: (w,b) for down, up, right, left
// --------------------------------------------------------------------------
extern "C" void kernel_launch(void* const* d_in, const int* in_sizes, int n_in,
                              void* d_out, int out_size) {
    (void)in_sizes; (void)n_in; (void)out_size;
    const float* x = (const float*)d_in[0];

    LstmParams LP;
    for (int l = 0; l < 4; l++) {
        LP.Wih[l]  = (const float*)d_in[1 + 3 * l];
        LP.Whh[l]  = (const float*)d_in[2 + 3 * l];
        LP.bias[l] = (const float*)d_in[3 + 3 * l];
    }
    ConvParams CP;
    for (int k = 0; k < 4; k++) {
        CP.w[k] = (const float*)d_in[13 + 2 * k];
        CP.b[k] = (const float*)d_in[14 + 2 * k];
    }

    const int lstm_smem = (3 * 128 * ROWP) * 4 + 32768;   // 88064 B (2 CTAs/SM)
    cudaFuncSetAttribute(lstm_kernel, cudaFuncAttributeMaxDynamicSharedMemorySize, lstm_smem);

    pack_lstm_kernel<<<dim3(128, 4), 256>>>(LP);
    pack_conv_kernel<<<dim3(16, 4), 256>>>(CP);
    transpose_kernel<<<2048, 256>>>(x);
    lstm_kernel<<<dim3(64, 4), 512, lstm_smem>>>(LP);
    conv_kernel<<<dim3(4096, 4), 128>>>(CP, (float*)d_out);
}